// round 12
// baseline (speedup 1.0000x reference)
#include <cuda_runtime.h>
#include <cuda_bf16.h>
#include <cstdint>
#include <cstddef>

#define Ltok 768
#define Ddim 1024
#define DPd  128
#define Pp   64
#define Hd   128
#define NBd  64
#define NKB  32   // split-K slices in k_down

__device__ float g_q [Ltok * Pp];
__device__ float g_k [Ltok * Pp];
__device__ float g_Dq[Ltok * Hd];
__device__ float g_Dk[Ltok * Hd];
__device__ float g_part[NKB * Ltok * DPd];
__device__ float g_W1t [Hd * Pp];    // tf32-rounded W1 prod half, [h][p]
__device__ float g_W2gt[NBd * Hd];   // tf32-rounded (ln_g * W2), [n][h]
__device__ float g_Gvec[NBd];
__device__ float g_Cvec[NBd];

__device__ __forceinline__ unsigned long long pack2(float lo, float hi) {
    unsigned long long r;
    asm("mov.b64 %0, {%1, %2};" : "=l"(r) : "f"(lo), "f"(hi));
    return r;
}
__device__ __forceinline__ void unpack2(unsigned long long v, float& lo, float& hi) {
    asm("mov.b64 {%0, %1}, %2;" : "=f"(lo), "=f"(hi) : "l"(v));
}
__device__ __forceinline__ void ffma2(unsigned long long& acc,
                                      unsigned long long a, unsigned long long b) {
    asm("fma.rn.f32x2 %0, %1, %2, %0;" : "+l"(acc) : "l"(a), "l"(b));
}
__device__ __forceinline__ uint32_t s2u(const void* p) {
    uint32_t a;
    asm("{ .reg .u64 t; cvta.to.shared.u64 t, %1; cvt.u32.u64 %0, t; }" : "=r"(a) : "l"(p));
    return a;
}
__device__ __forceinline__ uint32_t f2tf(float x) {
    uint32_t r;
    asm("cvt.rna.tf32.f32 %0, %1;" : "=r"(r) : "f"(x));
    return r;
}
#define LDSM4(r, addr) \
    asm volatile("ldmatrix.sync.aligned.m8n8.x4.shared.b16 {%0,%1,%2,%3}, [%4];" \
        : "=r"((r)[0]), "=r"((r)[1]), "=r"((r)[2]), "=r"((r)[3]) : "r"(addr))
#define MMAT(c, a, b0, b1) \
    asm volatile("mma.sync.aligned.m16n8k8.row.col.f32.tf32.tf32.f32 " \
        "{%0,%1,%2,%3}, {%4,%5,%6,%7}, {%8,%9}, {%0,%1,%2,%3};" \
        : "+f"((c)[0]), "+f"((c)[1]), "+f"((c)[2]), "+f"((c)[3]) \
        : "r"((a)[0]), "r"((a)[1]), "r"((a)[2]), "r"((a)[3]), "r"(b0), "r"(b1))

__device__ __forceinline__ float gelu_exact(float x) {
    return 0.5f * x * (1.0f + erff(x * 0.70710678118654752f));
}

// ===================== kernel 1: down-proj split-K partials ==================
// grid (12, 32): 64 rows x 128 cols per block, K-slice of 32.
__global__ __launch_bounds__(256) void k_down(const float* __restrict__ x,
                                              const float* __restrict__ Wd) {
    __shared__ float xs[64][36];
    __shared__ float ws[32][132];
    const int t = threadIdx.x, tx = t & 15, ty = t >> 4;
    const int m0 = blockIdx.x * 64, kb = blockIdx.y;
    unsigned long long acc[4][4];
#pragma unroll
    for (int u = 0; u < 4; u++)
#pragma unroll
        for (int v = 0; v < 4; v++) acc[u][v] = 0ull;
    const int d0 = kb * 32;
    for (int idx = t; idx < 64 * 32; idx += 256) {
        int kk = idx & 31, mm = idx >> 5;
        xs[mm][kk] = x[(size_t)(m0 + mm) * Ddim + d0 + kk];
    }
    for (int idx = t; idx < 32 * 128; idx += 256) {
        int kk = idx & 31, p = idx >> 5;
        ws[kk][p] = Wd[(size_t)p * Ddim + d0 + kk];
    }
    __syncthreads();
#pragma unroll
    for (int k = 0; k < 32; k += 4) {
        float4 a4[4];
#pragma unroll
        for (int u = 0; u < 4; u++) a4[u] = *(const float4*)&xs[ty * 4 + u][k];
#pragma unroll
        for (int kk = 0; kk < 4; kk++) {
            const float* wrow = &ws[k + kk][tx * 8];
            ulonglong2 b0 = *(const ulonglong2*)(wrow);
            ulonglong2 b1 = *(const ulonglong2*)(wrow + 4);
#pragma unroll
            for (int u = 0; u < 4; u++) {
                float av = (&a4[u].x)[kk];
                unsigned long long ad = pack2(av, av);
                ffma2(acc[u][0], ad, b0.x);
                ffma2(acc[u][1], ad, b0.y);
                ffma2(acc[u][2], ad, b1.x);
                ffma2(acc[u][3], ad, b1.y);
            }
        }
    }
    float* part = &g_part[(size_t)kb * Ltok * DPd];
#pragma unroll
    for (int u = 0; u < 4; u++) {
        int m = m0 + ty * 4 + u;
#pragma unroll
        for (int vp = 0; vp < 4; vp++) {
            float lo, hi;
            unpack2(acc[u][vp], lo, hi);
            part[m * DPd + tx * 8 + vp * 2]     = lo;
            part[m * DPd + tx * 8 + vp * 2 + 1] = hi;
        }
    }
}

// ===================== kernel 2 (fused mid) ===================================
__global__ __launch_bounds__(128) void k_mid(const float* __restrict__ bd,
                                             const float* __restrict__ W1,
                                             const float* __restrict__ b1,
                                             const float* __restrict__ W2,
                                             const float* __restrict__ lng,
                                             const float* __restrict__ lnb,
                                             const float* __restrict__ b2) {
    const int blk = blockIdx.x, t = threadIdx.x;
    if (blk < Ltok) {
        const int l = blk;
        __shared__ float qs[64], ks[64];
        float s = bd[t];
        const int idx = l * DPd + t;
#pragma unroll
        for (int r = 0; r < NKB; r++) s += g_part[(size_t)r * Ltok * DPd + idx];
        if (t < 64) { qs[t] = s;      g_q[l * Pp + t] = s; }
        else        { ks[t - 64] = s; g_k[l * Pp + (t - 64)] = s; }
        __syncthreads();
        float aq = b1[t], ak = 0.f;
        const float4* w4 = (const float4*)&W1[(size_t)t * DPd + Pp];
#pragma unroll
        for (int p4 = 0; p4 < 16; p4++) {
            float4 w = w4[p4];
            int b = p4 * 4;
            aq = fmaf(w.x, qs[b + 0], aq); ak = fmaf(w.x, ks[b + 0], ak);
            aq = fmaf(w.y, qs[b + 1], aq); ak = fmaf(w.y, ks[b + 1], ak);
            aq = fmaf(w.z, qs[b + 2], aq); ak = fmaf(w.z, ks[b + 2], ak);
            aq = fmaf(w.w, qs[b + 3], aq); ak = fmaf(w.w, ks[b + 3], ak);
        }
        g_Dq[l * Hd + t] = aq;
        g_Dk[l * Hd + t] = ak;
    } else if (blk < Ltok + 64) {
        int i = (blk - Ltok) * 128 + t;
        int h = i >> 6, p = i & 63;
        g_W1t[i] = __uint_as_float(f2tf(W1[(size_t)h * DPd + p]));
    } else if (blk < Ltok + 128) {
        int i = (blk - Ltok - 64) * 128 + t;
        g_W2gt[i] = __uint_as_float(f2tf(W2[i] * lng[i & 127]));
    } else {
        if (t < NBd) {
            float G = 0.f, C = 0.f;
            const float* wr = &W2[(size_t)t * Hd];
#pragma unroll 4
            for (int h = 0; h < Hd; h++) {
                float w = wr[h];
                G = fmaf(w, lng[h], G);
                C = fmaf(w, lnb[h], C);
            }
            g_Gvec[t] = G;
            g_Cvec[t] = C + b2[t];
        }
    }
}

// ===================== kernel 3: TF32 mma.sync fused main =====================
// CTA = 64 pairs (8i x 8j), 256 threads, 8 warps.
// Warp w: pair-group g = w>>1 (16 pairs), h-half hh = w&1.
// GEMM1: warp = 16 pairs x 64 h (acc1 32 regs); LN stats combined via sred.
// GEMM2: warp = 16 pairs x 32 n, full K=128 (acc2 16 regs).
// SMEM (bytes): 0 dq_s 8x136f (4352) | 4352 dk_s 8x136f (4352)
//   8704 sred 64x16B (1024) | 9728 Gs 256 | 9984 Cs 256
//   stage1: 10240 A1 16K (64 rows x 256B) | 26624 B1 32K (128 rows x 256B)
//   stage2 overlay: 10240 A2 32K (64 rows x 512B) | 43008 B2 32K (64 rows x 512B)
//   total 75776  -> 3 CTAs/SM
#define OFF_DQ    0
#define OFF_DK    4352
#define OFF_SRED  8704
#define OFF_GS    9728
#define OFF_CS    9984
#define OFF_A1    10240
#define OFF_B1    26624
#define OFF_A2    10240
#define OFF_B2    43008
#define SMEM_MAIN 75776

__global__ __launch_bounds__(256, 3) void k_main(float* __restrict__ out) {
    extern __shared__ char smc[];
    const uint32_t sb = s2u(smc);
    const int t = threadIdx.x, wid = t >> 5, lid = t & 31;
    const int gid = lid >> 2, tig = lid & 3;
    const int grp = wid >> 1, hh = wid & 1;
    const int j0 = blockIdx.x * 8;
    const int i0 = blockIdx.y * 8;

    float* dq_s = (float*)(smc + OFF_DQ);
    float* dk_s = (float*)(smc + OFF_DK);
    float* Gs   = (float*)(smc + OFF_GS);
    float* Cs   = (float*)(smc + OFF_CS);

    // ---- prologue fills ----
    // A1: hin = q*k tf32, 64 rows x 256B
    for (int idx = t; idx < 64 * 32; idx += 256) {
        int pair = idx >> 5, p = (idx & 31) * 2;
        int jj = pair & 7, ii = pair >> 3;
        float2 qv = *(const float2*)&g_q[(j0 + jj) * 64 + p];
        float2 kv = *(const float2*)&g_k[(i0 + ii) * 64 + p];
        uint2 v;
        v.x = f2tf(qv.x * kv.x);
        v.y = f2tf(qv.y * kv.y);
        uint32_t byte = (uint32_t)(pair * 256 + (((p >> 2) ^ (pair & 7)) << 4) + ((p & 3) << 2));
        *(uint2*)(smc + OFF_A1 + byte) = v;
    }
    // B1: W1t [h][p], 128 rows x 256B
    for (int idx = t; idx < 128 * 16; idx += 256) {
        int h = idx >> 4, c4 = idx & 15;
        uint32_t byte = (uint32_t)(h * 256 + ((c4 ^ (h & 7)) << 4));
        *(float4*)(smc + OFF_B1 + byte) = *(const float4*)&g_W1t[h * 64 + c4 * 4];
    }
    // dq/dk: 8 rows x 128, stride 136
    {
        int jj = t >> 5, c4 = t & 31;
        *(float4*)&dq_s[jj * 136 + c4 * 4] = *(const float4*)&g_Dq[(j0 + jj) * 128 + c4 * 4];
        *(float4*)&dk_s[jj * 136 + c4 * 4] = *(const float4*)&g_Dk[(i0 + jj) * 128 + c4 * 4];
    }
    if (t < 64)       Gs[t] = g_Gvec[t];
    else if (t < 128) Cs[t - 64] = g_Cvec[t - 64];
    __syncthreads();

    // ---- GEMM1: acc1[8 local n-tiles][4], K=64 = 8 k8-steps ----
    float acc1[8][4];
#pragma unroll
    for (int n = 0; n < 8; n++)
#pragma unroll
        for (int c = 0; c < 4; c++) acc1[n][c] = 0.f;

    const int arow = grp * 16 + (lid & 15);
    const int nro1 = hh * 64 + (lid & 7) + ((lid >> 4) << 3);
#pragma unroll
    for (int ks = 0; ks < 8; ks++) {
        uint32_t a[4];
        {
            int chunk = ks * 2 + (lid >> 4);
            uint32_t ad = sb + OFF_A1 + arow * 256 + ((chunk ^ (arow & 7)) << 4);
            LDSM4(a, ad);
        }
        int bch = ks * 2 + ((lid >> 3) & 1);
#pragma unroll
        for (int np = 0; np < 4; np++) {
            int brow = nro1 + np * 16;
            uint32_t bd = sb + OFF_B1 + brow * 256 + ((bch ^ (brow & 7)) << 4);
            uint32_t b[4];
            LDSM4(b, bd);
            MMAT(acc1[2 * np],     a, b[0], b[1]);
            MMAT(acc1[2 * np + 1], a, b[2], b[3]);
        }
    }

    // ---- epilogue A: +Dq-Dk, exact GELU, partial stats ----
    float sA[2], s2A[2];
#pragma unroll
    for (int r = 0; r < 2; r++) {
        int pair = grp * 16 + gid + 8 * r;        // jj = gid, ii = pair>>3
        const float* dqr = &dq_s[gid * 136];
        const float* dkr = &dk_s[(pair >> 3) * 136];
        float s = 0.f, s2 = 0.f;
#pragma unroll
        for (int nt = 0; nt < 8; nt++) {
            int col = hh * 64 + nt * 8 + tig * 2;
            float2 dq = *(const float2*)&dqr[col];
            float2 dk = *(const float2*)&dkr[col];
            float g0 = gelu_exact(acc1[nt][2 * r]     + dq.x - dk.x);
            float g1 = gelu_exact(acc1[nt][2 * r + 1] + dq.y - dk.y);
            s += g0 + g1; s2 += g0 * g0 + g1 * g1;
            acc1[nt][2 * r] = g0; acc1[nt][2 * r + 1] = g1;
        }
        s  += __shfl_xor_sync(0xffffffffu, s, 1);
        s  += __shfl_xor_sync(0xffffffffu, s, 2);
        s2 += __shfl_xor_sync(0xffffffffu, s2, 1);
        s2 += __shfl_xor_sync(0xffffffffu, s2, 2);
        sA[r] = s; s2A[r] = s2;
        if (tig == 0)
            *(float2*)(smc + OFF_SRED + pair * 16 + hh * 8) = make_float2(s, s2);
    }
    __syncthreads();   // sred ready AND all stage-1 reads done

    float mu[2], rs[2];
#pragma unroll
    for (int r = 0; r < 2; r++) {
        int pair = grp * 16 + gid + 8 * r;
        float2 oth = *(const float2*)(smc + OFF_SRED + pair * 16 + (1 - hh) * 8);
        float S = sA[r] + oth.x, S2 = s2A[r] + oth.y;
        mu[r] = S * (1.0f / 128.0f);
        float var = S2 * (1.0f / 128.0f) - mu[r] * mu[r];
        rs[r] = rsqrtf(var + 1e-5f);
    }

    // ---- epilogue B: tf32 gelu(h) -> A2 (64 rows x 512B) ----
#pragma unroll
    for (int r = 0; r < 2; r++) {
        int row = grp * 16 + gid + 8 * r;
        uint32_t rbase = (uint32_t)(row * 512);
        uint32_t rx = (uint32_t)(row & 7);
#pragma unroll
        for (int nt = 0; nt < 8; nt++) {
            int col = hh * 64 + nt * 8 + tig * 2;
            uint2 v;
            v.x = f2tf(acc1[nt][2 * r]);
            v.y = f2tf(acc1[nt][2 * r + 1]);
            uint32_t chunk = (uint32_t)(col >> 2);
            uint32_t byte = rbase + ((chunk ^ rx) << 4) + ((uint32_t)(tig & 1) << 3);
            *(uint2*)(smc + OFF_A2 + byte) = v;
        }
    }
    // B2 fill: W2gt [n][h], 64 rows x 512B (overlays B1)
    for (int idx = t; idx < 64 * 32; idx += 256) {
        int n = idx >> 5, c4 = idx & 31;
        uint32_t byte = (uint32_t)(n * 512 + ((c4 ^ (n & 7)) << 4));
        *(float4*)(smc + OFF_B2 + byte) = *(const float4*)&g_W2gt[n * 128 + c4 * 4];
    }
    __syncthreads();

    // ---- GEMM2: acc2[4 local n-tiles][4], K=128 = 16 k8-steps ----
    float acc2[4][4];
#pragma unroll
    for (int n = 0; n < 4; n++)
#pragma unroll
        for (int c = 0; c < 4; c++) acc2[n][c] = 0.f;

    const int nro2 = hh * 32 + (lid & 7) + ((lid >> 4) << 3);
#pragma unroll
    for (int ks = 0; ks < 16; ks++) {
        uint32_t a[4];
        {
            int chunk = ks * 2 + (lid >> 4);
            uint32_t ad = sb + OFF_A2 + arow * 512 + ((chunk ^ (arow & 7)) << 4);
            LDSM4(a, ad);
        }
        int bch = ks * 2 + ((lid >> 3) & 1);
#pragma unroll
        for (int np = 0; np < 2; np++) {
            int brow = nro2 + np * 16;
            uint32_t bd = sb + OFF_B2 + brow * 512 + ((bch ^ (brow & 7)) << 4);
            uint32_t b[4];
            LDSM4(b, bd);
            MMAT(acc2[2 * np],     a, b[0], b[1]);
            MMAT(acc2[2 * np + 1], a, b[2], b[3]);
        }
    }

    // ---- output: rstd*(acc2 - mu*G) + C ----
#pragma unroll
    for (int r = 0; r < 2; r++) {
        int pair = grp * 16 + gid + 8 * r;
        int ii = pair >> 3, jj = gid;
        float* op = &out[((size_t)(i0 + ii) * Ltok + (j0 + jj)) * NBd];
#pragma unroll
        for (int nt = 0; nt < 4; nt++) {
            int col = hh * 32 + nt * 8 + tig * 2;
            float2 G2 = *(const float2*)&Gs[col];
            float2 C2 = *(const float2*)&Cs[col];
            float2 o;
            o.x = rs[r] * (acc2[nt][2 * r]     - mu[r] * G2.x) + C2.x;
            o.y = rs[r] * (acc2[nt][2 * r + 1] - mu[r] * G2.y) + C2.y;
            *(float2*)&op[col] = o;
        }
    }
}

// =============================================================================
extern "C" void kernel_launch(void* const* d_in, const int* in_sizes, int n_in,
                              void* d_out, int out_size) {
    const float* x   = (const float*)d_in[0];
    const float* Wd  = (const float*)d_in[1];
    const float* bd  = (const float*)d_in[2];
    const float* W1  = (const float*)d_in[3];
    const float* b1  = (const float*)d_in[4];
    const float* lng = (const float*)d_in[5];
    const float* lnb = (const float*)d_in[6];
    const float* W2  = (const float*)d_in[7];
    const float* b2  = (const float*)d_in[8];
    float* out = (float*)d_out;

    cudaFuncSetAttribute(k_main, cudaFuncAttributeMaxDynamicSharedMemorySize, SMEM_MAIN);

    k_down<<<dim3(12, NKB), 256>>>(x, Wd);
    k_mid <<<Ltok + 129, 128>>>(bd, W1, b1, W2, lng, lnb, b2);
    k_main<<<dim3(96, 96), 256, SMEM_MAIN>>>(out);
}

// round 13
// speedup vs baseline: 1.2023x; 1.2023x over previous
#include <cuda_runtime.h>
#include <cuda_fp16.h>
#include <cstdint>
#include <cstddef>

#define Ltok 768
#define Ddim 1024
#define DPd  128
#define Pp   64
#define Hd   128
#define NBd  64
#define NKB  16   // split-K slices in k_down

__device__ float g_q [Ltok * Pp];
__device__ float g_k [Ltok * Pp];
__device__ float g_Dq[Ltok * Hd];
__device__ float g_Dk[Ltok * Hd];
__device__ float g_part[NKB * Ltok * DPd];
__device__ __half g_W1h [Hd * Pp];    // fp16 W1 prod half, [h][p]
__device__ __half g_W2gh[NBd * Hd];   // fp16 (ln_g * W2), [n][h]
__device__ float g_Gvec[NBd];
__device__ float g_Cvec[NBd];

__device__ __forceinline__ unsigned long long pack2(float lo, float hi) {
    unsigned long long r;
    asm("mov.b64 %0, {%1, %2};" : "=l"(r) : "f"(lo), "f"(hi));
    return r;
}
__device__ __forceinline__ void unpack2(unsigned long long v, float& lo, float& hi) {
    asm("mov.b64 {%0, %1}, %2;" : "=f"(lo), "=f"(hi) : "l"(v));
}
__device__ __forceinline__ void ffma2(unsigned long long& acc,
                                      unsigned long long a, unsigned long long b) {
    asm("fma.rn.f32x2 %0, %1, %2, %0;" : "+l"(acc) : "l"(a), "l"(b));
}
__device__ __forceinline__ uint32_t s2u(const void* p) {
    uint32_t a;
    asm("{ .reg .u64 t; cvta.to.shared.u64 t, %1; cvt.u32.u64 %0, t; }" : "=r"(a) : "l"(p));
    return a;
}
#define LDSM4(r, addr) \
    asm volatile("ldmatrix.sync.aligned.m8n8.x4.shared.b16 {%0,%1,%2,%3}, [%4];" \
        : "=r"((r)[0]), "=r"((r)[1]), "=r"((r)[2]), "=r"((r)[3]) : "r"(addr))
#define MMAH(c, a, b0, b1) \
    asm volatile("mma.sync.aligned.m16n8k16.row.col.f32.f16.f16.f32 " \
        "{%0,%1,%2,%3}, {%4,%5,%6,%7}, {%8,%9}, {%0,%1,%2,%3};" \
        : "+f"((c)[0]), "+f"((c)[1]), "+f"((c)[2]), "+f"((c)[3]) \
        : "r"((a)[0]), "r"((a)[1]), "r"((a)[2]), "r"((a)[3]), "r"(b0), "r"(b1))

__device__ __forceinline__ float gelu_exact(float x) {
    return 0.5f * x * (1.0f + erff(x * 0.70710678118654752f));
}

// ===================== kernel 1: down-proj split-K partials ==================
// grid (12, 16): 64 rows x 128 cols per block, K-slice of 64.
__global__ __launch_bounds__(256) void k_down(const float* __restrict__ x,
                                              const float* __restrict__ Wd) {
    __shared__ float xs[64][36];
    __shared__ float ws[32][132];
    const int t = threadIdx.x, tx = t & 15, ty = t >> 4;
    const int m0 = blockIdx.x * 64, kb = blockIdx.y;
    unsigned long long acc[4][4];
#pragma unroll
    for (int u = 0; u < 4; u++)
#pragma unroll
        for (int v = 0; v < 4; v++) acc[u][v] = 0ull;
    const int dbeg = kb * 64;
    for (int d0 = dbeg; d0 < dbeg + 64; d0 += 32) {
        __syncthreads();
        for (int idx = t; idx < 64 * 32; idx += 256) {
            int kk = idx & 31, mm = idx >> 5;
            xs[mm][kk] = x[(size_t)(m0 + mm) * Ddim + d0 + kk];
        }
        for (int idx = t; idx < 32 * 128; idx += 256) {
            int kk = idx & 31, p = idx >> 5;
            ws[kk][p] = Wd[(size_t)p * Ddim + d0 + kk];
        }
        __syncthreads();
#pragma unroll
        for (int k = 0; k < 32; k += 4) {
            float4 a4[4];
#pragma unroll
            for (int u = 0; u < 4; u++) a4[u] = *(const float4*)&xs[ty * 4 + u][k];
#pragma unroll
            for (int kk = 0; kk < 4; kk++) {
                const float* wrow = &ws[k + kk][tx * 8];
                ulonglong2 b0 = *(const ulonglong2*)(wrow);
                ulonglong2 b1 = *(const ulonglong2*)(wrow + 4);
#pragma unroll
                for (int u = 0; u < 4; u++) {
                    float av = (&a4[u].x)[kk];
                    unsigned long long ad = pack2(av, av);
                    ffma2(acc[u][0], ad, b0.x);
                    ffma2(acc[u][1], ad, b0.y);
                    ffma2(acc[u][2], ad, b1.x);
                    ffma2(acc[u][3], ad, b1.y);
                }
            }
        }
    }
    float* part = &g_part[(size_t)kb * Ltok * DPd];
#pragma unroll
    for (int u = 0; u < 4; u++) {
        int m = m0 + ty * 4 + u;
#pragma unroll
        for (int vp = 0; vp < 4; vp++) {
            float lo, hi;
            unpack2(acc[u][vp], lo, hi);
            part[m * DPd + tx * 8 + vp * 2]     = lo;
            part[m * DPd + tx * 8 + vp * 2 + 1] = hi;
        }
    }
}

// ===================== kernel 2 (fused mid) ===================================
// blocks 0..767   : row l — split-K reduce + bias -> q,k ; then Dq/Dk
// blocks 768..831 : W1 prod-half fp16 (8192 elems)
// blocks 832..895 : (ln_g * W2) fp16 (8192 elems)
// block  896      : G[n], C[n]
__global__ __launch_bounds__(128) void k_mid(const float* __restrict__ bd,
                                             const float* __restrict__ W1,
                                             const float* __restrict__ b1,
                                             const float* __restrict__ W2,
                                             const float* __restrict__ lng,
                                             const float* __restrict__ lnb,
                                             const float* __restrict__ b2) {
    const int blk = blockIdx.x, t = threadIdx.x;
    if (blk < Ltok) {
        const int l = blk;
        __shared__ float qs[64], ks[64];
        float s = bd[t];
        const int idx = l * DPd + t;
#pragma unroll
        for (int r = 0; r < NKB; r++) s += g_part[(size_t)r * Ltok * DPd + idx];
        if (t < 64) { qs[t] = s;      g_q[l * Pp + t] = s; }
        else        { ks[t - 64] = s; g_k[l * Pp + (t - 64)] = s; }
        __syncthreads();
        float aq = b1[t], ak = 0.f;
        const float4* w4 = (const float4*)&W1[(size_t)t * DPd + Pp];
#pragma unroll
        for (int p4 = 0; p4 < 16; p4++) {
            float4 w = w4[p4];
            int b = p4 * 4;
            aq = fmaf(w.x, qs[b + 0], aq); ak = fmaf(w.x, ks[b + 0], ak);
            aq = fmaf(w.y, qs[b + 1], aq); ak = fmaf(w.y, ks[b + 1], ak);
            aq = fmaf(w.z, qs[b + 2], aq); ak = fmaf(w.z, ks[b + 2], ak);
            aq = fmaf(w.w, qs[b + 3], aq); ak = fmaf(w.w, ks[b + 3], ak);
        }
        g_Dq[l * Hd + t] = aq;
        g_Dk[l * Hd + t] = ak;
    } else if (blk < Ltok + 64) {
        int i = (blk - Ltok) * 128 + t;
        int h = i >> 6, p = i & 63;
        g_W1h[i] = __float2half_rn(W1[(size_t)h * DPd + p]);
    } else if (blk < Ltok + 128) {
        int i = (blk - Ltok - 64) * 128 + t;     // i = n*128 + h
        g_W2gh[i] = __float2half_rn(W2[i] * lng[i & 127]);
    } else {
        if (t < NBd) {
            float G = 0.f, C = 0.f;
            const float* wr = &W2[(size_t)t * Hd];
#pragma unroll 4
            for (int h = 0; h < Hd; h++) {
                float w = wr[h];
                G = fmaf(w, lng[h], G);
                C = fmaf(w, lnb[h], C);
            }
            g_Gvec[t] = G;
            g_Cvec[t] = C + b2[t];
        }
    }
}

// ===================== kernel 3: 1-term FP16 mma.sync fused main ==============
// CTA = 128 pairs (16 j x 8 i), 256 threads, 8 warps; warp w = i-row w, 16 pairs.
// out = rstd*(gelu(h) @ (g*W2)^T - mu*G) + C
// SMEM (bytes): 0 dq_s 16x132f (8448) | 8448 dk_s 8x132f (4224)
//   12672 Gs 256 | 12928 Cs 256
//   stage1: 14336 A1 16K (128B rows) | 30720 B1 16K (128B rows)
//   stage2 overlay: 14336 A2 32K (256B rows) ; persistent: 47104 B2 16K (256B rows)
//   total 63488 (2 CTAs/SM; reg-limited anyway)
#define OFF_DQ   0
#define OFF_DK   8448
#define OFF_GS   12672
#define OFF_CS   12928
#define OFF_A1   14336
#define OFF_B1   30720
#define OFF_A2   14336
#define OFF_B2   47104
#define SMEM_MAIN 63488

__global__ __launch_bounds__(256, 2) void k_main(float* __restrict__ out) {
    extern __shared__ char smc[];
    const uint32_t sb = s2u(smc);
    const int t = threadIdx.x, wid = t >> 5, lid = t & 31;
    const int gid = lid >> 2, tig = lid & 3;
    const int j0 = blockIdx.x * 16;
    const int i0 = blockIdx.y * 8;

    float* dq_s = (float*)(smc + OFF_DQ);
    float* dk_s = (float*)(smc + OFF_DK);
    float* Gs   = (float*)(smc + OFF_GS);
    float* Cs   = (float*)(smc + OFF_CS);

    // ---- prologue fills ----
    // A1: hin = q*k fp16, 128 rows x 128B, chunk ^= row&7
    for (int idx = t; idx < 128 * 32; idx += 256) {
        int pair = idx >> 5, p = (idx & 31) * 2;
        int jj = pair & 15, ii = pair >> 4;
        float2 qv = *(const float2*)&g_q[(j0 + jj) * 64 + p];
        float2 kv = *(const float2*)&g_k[(i0 + ii) * 64 + p];
        __half2 v = __floats2half2_rn(qv.x * kv.x, qv.y * kv.y);
        uint32_t byte = (uint32_t)(pair * 128 + (((p >> 3) ^ (pair & 7)) << 4) + ((p & 7) << 1));
        *(__half2*)(smc + OFF_A1 + byte) = v;
    }
    // B1: W1h [h][p], 128 rows x 128B
    {
        const uint32_t* wh = (const uint32_t*)g_W1h;
        for (int idx = t; idx < 128 * 32; idx += 256) {
            int h = idx >> 5, p = (idx & 31) * 2;
            uint32_t byte = (uint32_t)(h * 128 + (((p >> 3) ^ (h & 7)) << 4) + ((p & 7) << 1));
            *(uint32_t*)(smc + OFF_B1 + byte) = wh[idx];
        }
    }
    // B2: W2gh [n][h], 64 rows x 256B (persistent region)
    {
        const uint32_t* wh = (const uint32_t*)g_W2gh;
        for (int idx = t; idx < 64 * 64; idx += 256) {
            int n = idx >> 6, h = (idx & 63) * 2;
            uint32_t byte = (uint32_t)(n * 256 + (((h >> 3) ^ (n & 7)) << 4) + ((h & 7) << 1));
            *(uint32_t*)(smc + OFF_B2 + byte) = wh[idx];
        }
    }
    for (int idx = t; idx < 16 * 32; idx += 256) {
        int jj = idx >> 5, c4 = idx & 31;
        *(float4*)&dq_s[jj * 132 + c4 * 4] = *(const float4*)&g_Dq[(j0 + jj) * 128 + c4 * 4];
    }
    for (int idx = t; idx < 8 * 32; idx += 256) {
        int ii = idx >> 5, c4 = idx & 31;
        *(float4*)&dk_s[ii * 132 + c4 * 4] = *(const float4*)&g_Dk[(i0 + ii) * 128 + c4 * 4];
    }
    if (t < 64)       Gs[t] = g_Gvec[t];
    else if (t < 128) Cs[t - 64] = g_Cvec[t - 64];
    __syncthreads();

    // ---- GEMM1: acc1[16 n-tiles][4], K=64 = 4 k16-steps, 1-term fp16 ----
    float acc1[16][4];
#pragma unroll
    for (int n = 0; n < 16; n++)
#pragma unroll
        for (int c = 0; c < 4; c++) acc1[n][c] = 0.f;

    const int pair0 = wid * 16;
#pragma unroll
    for (int ks = 0; ks < 4; ks++) {
        uint32_t a[4];
        {
            int row = pair0 + (lid & 15);
            int chunk = ks * 2 + (lid >> 4);
            uint32_t ad = sb + OFF_A1 + row * 128 + ((chunk ^ (row & 7)) << 4);
            LDSM4(a, ad);
        }
        int brow = (lid & 7) + ((lid >> 4) << 3);
        int bch = ks * 2 + ((lid >> 3) & 1);
#pragma unroll
        for (int np = 0; np < 8; np++) {
            int row = np * 16 + brow;
            uint32_t bd = sb + OFF_B1 + row * 128 + ((bch ^ (row & 7)) << 4);
            uint32_t b[4];
            LDSM4(b, bd);
            MMAH(acc1[2 * np],     a, b[0], b[1]);
            MMAH(acc1[2 * np + 1], a, b[2], b[3]);
        }
    }

    // ---- epilogue pass A: +Dq-Dk, exact GELU, row stats (4-lane shuffles) ----
    float mu[2], rs[2];
#pragma unroll
    for (int r = 0; r < 2; r++) {
        int prow = pair0 + gid + 8 * r;
        int jj = prow & 15;
        const float* dqr = &dq_s[jj * 132];
        const float* dkr = &dk_s[wid * 132];
        float s = 0.f, s2 = 0.f;
#pragma unroll
        for (int nt = 0; nt < 16; nt++) {
            int col = nt * 8 + tig * 2;
            float2 dq = *(const float2*)&dqr[col];
            float2 dk = *(const float2*)&dkr[col];
            float g0 = gelu_exact(acc1[nt][2 * r]     + dq.x - dk.x);
            float g1 = gelu_exact(acc1[nt][2 * r + 1] + dq.y - dk.y);
            s += g0 + g1; s2 += g0 * g0 + g1 * g1;
            acc1[nt][2 * r] = g0; acc1[nt][2 * r + 1] = g1;
        }
        s  += __shfl_xor_sync(0xffffffffu, s, 1);
        s  += __shfl_xor_sync(0xffffffffu, s, 2);
        s2 += __shfl_xor_sync(0xffffffffu, s2, 1);
        s2 += __shfl_xor_sync(0xffffffffu, s2, 2);
        mu[r] = s * (1.0f / 128.0f);
        float var = s2 * (1.0f / 128.0f) - mu[r] * mu[r];
        rs[r] = rsqrtf(var + 1e-5f);
    }
    __syncthreads();   // all warps done reading stage-1 tiles

    // ---- epilogue pass B: fp16 gelu(h) -> A2 (128 rows x 256B) ----
#pragma unroll
    for (int r = 0; r < 2; r++) {
        int prow = pair0 + gid + 8 * r;
        uint32_t rbase = (uint32_t)(prow * 256);
        uint32_t rx = (uint32_t)(prow & 7);
#pragma unroll
        for (int nt = 0; nt < 16; nt++) {
            int col = nt * 8 + tig * 2;
            __half2 v = __floats2half2_rn(acc1[nt][2 * r], acc1[nt][2 * r + 1]);
            uint32_t byte = rbase + ((((uint32_t)(col >> 3)) ^ rx) << 4) + ((col & 7) << 1);
            *(__half2*)(smc + OFF_A2 + byte) = v;
        }
    }
    __syncthreads();

    // ---- GEMM2: acc2[8 n-tiles][4], K=128 = 8 k16-steps, 1-term fp16 ----
    float acc2[8][4];
#pragma unroll
    for (int n = 0; n < 8; n++)
#pragma unroll
        for (int c = 0; c < 4; c++) acc2[n][c] = 0.f;

#pragma unroll
    for (int ks = 0; ks < 8; ks++) {
        uint32_t a[4];
        {
            int row = pair0 + (lid & 15);
            int chunk = ks * 2 + (lid >> 4);
            uint32_t ad = sb + OFF_A2 + row * 256 + ((chunk ^ (row & 7)) << 4);
            LDSM4(a, ad);
        }
        int brow = (lid & 7) + ((lid >> 4) << 3);
        int bch = ks * 2 + ((lid >> 3) & 1);
#pragma unroll
        for (int np = 0; np < 4; np++) {
            int row = np * 16 + brow;
            uint32_t bd = sb + OFF_B2 + row * 256 + ((bch ^ (row & 7)) << 4);
            uint32_t b[4];
            LDSM4(b, bd);
            MMAH(acc2[2 * np],     a, b[0], b[1]);
            MMAH(acc2[2 * np + 1], a, b[2], b[3]);
        }
    }

    // ---- output: rstd*(acc2 - mu*G) + C ----
#pragma unroll
    for (int r = 0; r < 2; r++) {
        int prow = pair0 + gid + 8 * r;
        int jj = prow & 15;
        float* op = &out[((size_t)(i0 + wid) * Ltok + (j0 + jj)) * NBd];
#pragma unroll
        for (int nt = 0; nt < 8; nt++) {
            int col = nt * 8 + tig * 2;
            float2 G2 = *(const float2*)&Gs[col];
            float2 C2 = *(const float2*)&Cs[col];
            float2 o;
            o.x = rs[r] * (acc2[nt][2 * r]     - mu[r] * G2.x) + C2.x;
            o.y = rs[r] * (acc2[nt][2 * r + 1] - mu[r] * G2.y) + C2.y;
            *(float2*)&op[col] = o;
        }
    }
}

// =============================================================================
extern "C" void kernel_launch(void* const* d_in, const int* in_sizes, int n_in,
                              void* d_out, int out_size) {
    const float* x   = (const float*)d_in[0];
    const float* Wd  = (const float*)d_in[1];
    const float* bd  = (const float*)d_in[2];
    const float* W1  = (const float*)d_in[3];
    const float* b1  = (const float*)d_in[4];
    const float* lng = (const float*)d_in[5];
    const float* lnb = (const float*)d_in[6];
    const float* W2  = (const float*)d_in[7];
    const float* b2  = (const float*)d_in[8];
    float* out = (float*)d_out;

    cudaFuncSetAttribute(k_main, cudaFuncAttributeMaxDynamicSharedMemorySize, SMEM_MAIN);

    k_down<<<dim3(12, NKB), 256>>>(x, Wd);
    k_mid <<<Ltok + 129, 128>>>(bd, W1, b1, W2, lng, lnb, b2);
    k_main<<<dim3(48, 96), 256, SMEM_MAIN>>>(out);
}